// round 1
// baseline (speedup 1.0000x reference)
#include <cuda_runtime.h>

// ---------------------------------------------------------------------------
// ENAS RNN, fixed DAG. fp32 SIMT baseline (round 0).
//   T=64, B=64, H=E=1000, V=10000, 11 edges.
// Per step: cell0 (K=2000 dual GEMM) -> 4 level kernels -> last-level kernel
// (fused leaf mean + h11 carry). Then one decoder GEMM.
// ---------------------------------------------------------------------------

namespace {

constexpr int Hd = 1000;
constexpr int Ed = 1000;
constexpr int Bb = 64;
constexpr int Tt = 64;
constexpr int Vv = 10000;

constexpr int KT = 50;             // K tile (divides 1000 and 2000)
constexpr int BN = 16;             // N tile
constexpr int NTILES = (Hd + BN - 1) / BN;  // 63

// Scratch (static device allocations are allowed; cudaMalloc is not).
__device__ float g_h[12][Bb * Hd];          // h[0..11] for current step
__device__ float g_c0[Bb * Hd];             // c0 of current step
__device__ float g_outs[Tt * Bb * Hd];      // per-step leaf means (decoder input)

__device__ __forceinline__ float sigmf(float x) { return 1.0f / (1.0f + expf(-x)); }

__device__ __forceinline__ float applyAct(int a, float v) {
    switch (a) {
        case 0: return fmaxf(v, 0.0f);   // relu
        case 1: return tanhf(v);         // tanh
        case 2: return sigmf(v);         // sigmoid
        default: return v;               // identity
    }
}

struct EdgeDesc { int parent; int child; int w; int act; };
struct LevelDesc { EdgeDesc e[3]; };

// ---------------------------------------------------------------------------
// cell0: c0 = sigmoid(xh @ w_xc^T + b_xc)
//        h0 = c0 * tanh(xh @ w_xh^T + b_xh) + (1-c0) * h_prev
// xh = [embed(token) , h_prev]  (K = 2000)
// Tile: BM=64 (all batch), BN=16, 128 threads, micro 4(b) x 2(n), dual dot.
// ---------------------------------------------------------------------------
__global__ __launch_bounds__(128) void cell0_kernel(
    const int* __restrict__ inputs, const float* __restrict__ hinit,
    const float* __restrict__ emb,
    const float* __restrict__ w_xh, const float* __restrict__ b_xh,
    const float* __restrict__ w_xc, const float* __restrict__ b_xc,
    int t)
{
    __shared__ __align__(16) float As[KT][68];
    __shared__ __align__(16) float Bh[KT][20];
    __shared__ __align__(16) float Bc[KT][20];
    __shared__ int toks[Bb];

    const float* __restrict__ hprev = (t == 0) ? hinit : g_h[11];

    const int tid = threadIdx.x;
    if (tid < Bb) toks[tid] = inputs[t * Bb + tid];

    const int n0g = blockIdx.x * BN;
    const int bl = (tid >> 3) * 4;   // 0..60
    const int nl = (tid & 7) * 2;    // 0..14

    float ah[4][2] = {}, ac[4][2] = {};

    for (int k0 = 0; k0 < Ed + Hd; k0 += KT) {
        __syncthreads();
        // A tile (transposed into [k][b]); a KT tile never straddles emb/h.
        for (int i = tid; i < Bb * KT; i += 128) {
            int bb = i / KT, kk = i % KT;
            float v;
            if (k0 < Ed) v = emb[toks[bb] * Ed + k0 + kk];
            else         v = hprev[bb * Hd + (k0 - Ed) + kk];
            As[kk][bb] = v;
        }
        // B tiles
        for (int i = tid; i < BN * KT; i += 128) {
            int nn = i / KT, kk = i % KT;
            int gn = n0g + nn;
            float vh = 0.0f, vc = 0.0f;
            if (gn < Hd) {
                vh = w_xh[gn * (Ed + Hd) + k0 + kk];
                vc = w_xc[gn * (Ed + Hd) + k0 + kk];
            }
            Bh[kk][nn] = vh;
            Bc[kk][nn] = vc;
        }
        __syncthreads();
#pragma unroll 10
        for (int kk = 0; kk < KT; ++kk) {
            float4 a4 = *reinterpret_cast<const float4*>(&As[kk][bl]);
            float2 h2 = *reinterpret_cast<const float2*>(&Bh[kk][nl]);
            float2 c2 = *reinterpret_cast<const float2*>(&Bc[kk][nl]);
            float av[4] = {a4.x, a4.y, a4.z, a4.w};
            float hv[2] = {h2.x, h2.y};
            float cv[2] = {c2.x, c2.y};
#pragma unroll
            for (int i = 0; i < 4; i++)
#pragma unroll
                for (int j = 0; j < 2; j++) {
                    ah[i][j] += av[i] * hv[j];
                    ac[i][j] += av[i] * cv[j];
                }
        }
    }

#pragma unroll
    for (int i = 0; i < 4; i++) {
        const int b = bl + i;
#pragma unroll
        for (int j = 0; j < 2; j++) {
            const int n = n0g + nl + j;
            if (n < Hd) {
                const int idx = b * Hd + n;
                float c0v = sigmf(ac[i][j] + b_xc[n]);
                float h0 = c0v * tanhf(ah[i][j] + b_xh[n]) + (1.0f - c0v) * hprev[idx];
                g_c0[idx] = c0v;
                g_h[0][idx] = h0;
            }
        }
    }
}

// ---------------------------------------------------------------------------
// One DAG level: up to 3 edges (blockIdx.y selects the edge).
// h[j] = sigmoid(h[i] @ Wc[e]^T) * act(h[i] @ Wh[e]^T) + (1-c0) * h[i]
// ---------------------------------------------------------------------------
__global__ __launch_bounds__(128) void level_kernel(
    LevelDesc L, const float* __restrict__ Wh, const float* __restrict__ Wc)
{
    __shared__ __align__(16) float As[KT][68];
    __shared__ __align__(16) float Bh[KT][20];
    __shared__ __align__(16) float Bc[KT][20];

    const EdgeDesc ed = L.e[blockIdx.y];
    const float* __restrict__ hin = g_h[ed.parent];
    float* __restrict__ hout = g_h[ed.child];
    const float* __restrict__ wh = Wh + (size_t)ed.w * Hd * Hd;
    const float* __restrict__ wc = Wc + (size_t)ed.w * Hd * Hd;

    const int tid = threadIdx.x;
    const int n0g = blockIdx.x * BN;
    const int bl = (tid >> 3) * 4;
    const int nl = (tid & 7) * 2;

    float ah[4][2] = {}, ac[4][2] = {};

    for (int k0 = 0; k0 < Hd; k0 += KT) {
        __syncthreads();
        for (int i = tid; i < Bb * KT; i += 128) {
            int bb = i / KT, kk = i % KT;
            As[kk][bb] = hin[bb * Hd + k0 + kk];
        }
        for (int i = tid; i < BN * KT; i += 128) {
            int nn = i / KT, kk = i % KT;
            int gn = n0g + nn;
            float vh = 0.0f, vc = 0.0f;
            if (gn < Hd) {
                vh = wh[gn * Hd + k0 + kk];
                vc = wc[gn * Hd + k0 + kk];
            }
            Bh[kk][nn] = vh;
            Bc[kk][nn] = vc;
        }
        __syncthreads();
#pragma unroll 10
        for (int kk = 0; kk < KT; ++kk) {
            float4 a4 = *reinterpret_cast<const float4*>(&As[kk][bl]);
            float2 h2 = *reinterpret_cast<const float2*>(&Bh[kk][nl]);
            float2 c2 = *reinterpret_cast<const float2*>(&Bc[kk][nl]);
            float av[4] = {a4.x, a4.y, a4.z, a4.w};
            float hv[2] = {h2.x, h2.y};
            float cv[2] = {c2.x, c2.y};
#pragma unroll
            for (int i = 0; i < 4; i++)
#pragma unroll
                for (int j = 0; j < 2; j++) {
                    ah[i][j] += av[i] * hv[j];
                    ac[i][j] += av[i] * cv[j];
                }
        }
    }

#pragma unroll
    for (int i = 0; i < 4; i++) {
        const int b = bl + i;
#pragma unroll
        for (int j = 0; j < 2; j++) {
            const int n = n0g + nl + j;
            if (n < Hd) {
                const int idx = b * Hd + n;
                float cj = sigmf(ac[i][j]);
                float v = applyAct(ed.act, ah[i][j]);
                hout[idx] = cj * v + (1.0f - g_c0[idx]) * hin[idx];
            }
        }
    }
}

// ---------------------------------------------------------------------------
// Last level: edges 8 (4->5, relu) and 9 (4->11, sigmoid), 4 dots per CTA,
// fused leaf mean:  out[t] = (h5+h7+h8+h9+h10+h11)/6, and h11 carried.
// ---------------------------------------------------------------------------
__global__ __launch_bounds__(128) void last_kernel(
    const float* __restrict__ Wh, const float* __restrict__ Wc, int t)
{
    __shared__ __align__(16) float As[KT][68];
    __shared__ __align__(16) float B5h[KT][20];
    __shared__ __align__(16) float B5c[KT][20];
    __shared__ __align__(16) float B9h[KT][20];
    __shared__ __align__(16) float B9c[KT][20];

    const float* __restrict__ hin = g_h[4];
    const float* __restrict__ wh5 = Wh + (size_t)8 * Hd * Hd;
    const float* __restrict__ wc5 = Wc + (size_t)8 * Hd * Hd;
    const float* __restrict__ wh9 = Wh + (size_t)9 * Hd * Hd;
    const float* __restrict__ wc9 = Wc + (size_t)9 * Hd * Hd;

    const int tid = threadIdx.x;
    const int n0g = blockIdx.x * BN;
    const int bl = (tid >> 3) * 4;
    const int nl = (tid & 7) * 2;

    float a5h[4][2] = {}, a5c[4][2] = {}, a9h[4][2] = {}, a9c[4][2] = {};

    for (int k0 = 0; k0 < Hd; k0 += KT) {
        __syncthreads();
        for (int i = tid; i < Bb * KT; i += 128) {
            int bb = i / KT, kk = i % KT;
            As[kk][bb] = hin[bb * Hd + k0 + kk];
        }
        for (int i = tid; i < BN * KT; i += 128) {
            int nn = i / KT, kk = i % KT;
            int gn = n0g + nn;
            float v0 = 0.0f, v1 = 0.0f, v2 = 0.0f, v3 = 0.0f;
            if (gn < Hd) {
                v0 = wh5[gn * Hd + k0 + kk];
                v1 = wc5[gn * Hd + k0 + kk];
                v2 = wh9[gn * Hd + k0 + kk];
                v3 = wc9[gn * Hd + k0 + kk];
            }
            B5h[kk][nn] = v0; B5c[kk][nn] = v1;
            B9h[kk][nn] = v2; B9c[kk][nn] = v3;
        }
        __syncthreads();
#pragma unroll 10
        for (int kk = 0; kk < KT; ++kk) {
            float4 a4 = *reinterpret_cast<const float4*>(&As[kk][bl]);
            float2 p0 = *reinterpret_cast<const float2*>(&B5h[kk][nl]);
            float2 p1 = *reinterpret_cast<const float2*>(&B5c[kk][nl]);
            float2 p2 = *reinterpret_cast<const float2*>(&B9h[kk][nl]);
            float2 p3 = *reinterpret_cast<const float2*>(&B9c[kk][nl]);
            float av[4] = {a4.x, a4.y, a4.z, a4.w};
            float w0[2] = {p0.x, p0.y};
            float w1[2] = {p1.x, p1.y};
            float w2[2] = {p2.x, p2.y};
            float w3[2] = {p3.x, p3.y};
#pragma unroll
            for (int i = 0; i < 4; i++)
#pragma unroll
                for (int j = 0; j < 2; j++) {
                    a5h[i][j] += av[i] * w0[j];
                    a5c[i][j] += av[i] * w1[j];
                    a9h[i][j] += av[i] * w2[j];
                    a9c[i][j] += av[i] * w3[j];
                }
        }
    }

#pragma unroll
    for (int i = 0; i < 4; i++) {
        const int b = bl + i;
#pragma unroll
        for (int j = 0; j < 2; j++) {
            const int n = n0g + nl + j;
            if (n < Hd) {
                const int idx = b * Hd + n;
                float om = 1.0f - g_c0[idx];
                float h4v = hin[idx];
                float h5 = sigmf(a5c[i][j]) * fmaxf(a5h[i][j], 0.0f) + om * h4v;
                float h11 = sigmf(a9c[i][j]) * sigmf(a9h[i][j]) + om * h4v;
                g_h[11][idx] = h11;
                g_outs[(size_t)t * Bb * Hd + idx] =
                    (h5 + h11 + g_h[7][idx] + g_h[8][idx] + g_h[9][idx] + g_h[10][idx]) * (1.0f / 6.0f);
            }
        }
    }
}

// ---------------------------------------------------------------------------
// Decoder: out[m][v] = sum_k g_outs[m][k] * dec_w[v][k] + dec_b[v]
// M=4096, N=10000, K=1000. 128x128 tile, 256 threads, 8x8 micro.
// ---------------------------------------------------------------------------
constexpr int DKT = 25;

__global__ __launch_bounds__(256, 1) void decoder_kernel(
    const float* __restrict__ dec_w, const float* __restrict__ dec_b,
    float* __restrict__ out)
{
    __shared__ __align__(16) float As[DKT][132];
    __shared__ __align__(16) float Bs[DKT][132];

    const int tid = threadIdx.x;
    const int m0g = blockIdx.y * 128;
    const int v0g = blockIdx.x * 128;
    const int ml = (tid >> 4) * 8;   // 0..120
    const int vl = (tid & 15) * 8;   // 0..120

    float acc[8][8] = {};

    for (int k0 = 0; k0 < Hd; k0 += DKT) {
        __syncthreads();
        for (int i = tid; i < 128 * DKT; i += 256) {
            int mm = i / DKT, kk = i % DKT;
            As[kk][mm] = g_outs[(size_t)(m0g + mm) * Hd + k0 + kk];
            int gv = v0g + mm;
            Bs[kk][mm] = (gv < Vv) ? dec_w[(size_t)gv * Hd + k0 + kk] : 0.0f;
        }
        __syncthreads();
#pragma unroll 5
        for (int kk = 0; kk < DKT; ++kk) {
            float a[8], b[8];
            *reinterpret_cast<float4*>(&a[0]) = *reinterpret_cast<const float4*>(&As[kk][ml]);
            *reinterpret_cast<float4*>(&a[4]) = *reinterpret_cast<const float4*>(&As[kk][ml + 4]);
            *reinterpret_cast<float4*>(&b[0]) = *reinterpret_cast<const float4*>(&Bs[kk][vl]);
            *reinterpret_cast<float4*>(&b[4]) = *reinterpret_cast<const float4*>(&Bs[kk][vl + 4]);
#pragma unroll
            for (int i = 0; i < 8; i++)
#pragma unroll
                for (int j = 0; j < 8; j++)
                    acc[i][j] += a[i] * b[j];
        }
    }

    if (v0g + 128 <= Vv) {
        // full tile: vectorized stores
#pragma unroll
        for (int i = 0; i < 8; i++) {
            const int m = m0g + ml + i;
#pragma unroll
            for (int jj = 0; jj < 2; jj++) {
                const int v = v0g + vl + jj * 4;
                float4 bb = *reinterpret_cast<const float4*>(&dec_b[v]);
                float4 r;
                r.x = acc[i][jj * 4 + 0] + bb.x;
                r.y = acc[i][jj * 4 + 1] + bb.y;
                r.z = acc[i][jj * 4 + 2] + bb.z;
                r.w = acc[i][jj * 4 + 3] + bb.w;
                *reinterpret_cast<float4*>(&out[(size_t)m * Vv + v]) = r;
            }
        }
    } else {
#pragma unroll
        for (int i = 0; i < 8; i++) {
            const int m = m0g + ml + i;
#pragma unroll
            for (int j = 0; j < 8; j++) {
                const int v = v0g + vl + j;
                if (v < Vv) out[(size_t)m * Vv + v] = acc[i][j] + dec_b[v];
            }
        }
    }
}

} // namespace

// ---------------------------------------------------------------------------
// Launch. 64 steps x 6 kernels + decoder. All plain launches (graph-capturable).
// ---------------------------------------------------------------------------
extern "C" void kernel_launch(void* const* d_in, const int* in_sizes, int n_in,
                              void* d_out, int out_size)
{
    (void)in_sizes; (void)n_in; (void)out_size;

    const int*   inputs = (const int*)  d_in[0];
    const float* hidden = (const float*)d_in[1];
    const float* emb    = (const float*)d_in[2];
    const float* w_xh   = (const float*)d_in[3];
    const float* b_xh   = (const float*)d_in[4];
    const float* w_xc   = (const float*)d_in[5];
    const float* b_xc   = (const float*)d_in[6];
    const float* Wh     = (const float*)d_in[7];
    const float* Wc     = (const float*)d_in[8];
    const float* dec_w  = (const float*)d_in[9];
    const float* dec_b  = (const float*)d_in[10];
    float* out = (float*)d_out;

    // DAG levels (edge index, parent, child, activation).
    // acts: 0=relu, 1=tanh, 2=sigmoid, 3=identity
    const LevelDesc LV1 = {{ {0, 1, 0, 0}, {0, 6, 1, 1},  {0, 0, 0, 3} }};
    const LevelDesc LV2 = {{ {1, 2, 2, 0}, {1, 8, 3, 2},  {6, 7, 10, 1} }};
    const LevelDesc LV3 = {{ {2, 3, 4, 1}, {2, 9, 5, 0},  {0, 0, 0, 3} }};
    const LevelDesc LV4 = {{ {3, 4, 6, 3}, {3, 10, 7, 1}, {0, 0, 0, 3} }};

    dim3 blk(128);
    for (int t = 0; t < Tt; ++t) {
        cell0_kernel<<<dim3(NTILES), blk>>>(inputs, hidden, emb, w_xh, b_xh, w_xc, b_xc, t);
        level_kernel<<<dim3(NTILES, 2), blk>>>(LV1, Wh, Wc);
        level_kernel<<<dim3(NTILES, 3), blk>>>(LV2, Wh, Wc);
        level_kernel<<<dim3(NTILES, 2), blk>>>(LV3, Wh, Wc);
        level_kernel<<<dim3(NTILES, 2), blk>>>(LV4, Wh, Wc);
        last_kernel<<<dim3(NTILES), blk>>>(Wh, Wc, t);
    }

    decoder_kernel<<<dim3((Vv + 127) / 128, (Tt * Bb) / 128), dim3(256)>>>(dec_w, dec_b, out);
}

// round 2
// speedup vs baseline: 3.5893x; 3.5893x over previous
#include <cuda_runtime.h>

// ---------------------------------------------------------------------------
// ENAS RNN, fixed DAG — round 2: f32x2 packed FMA + double-buffered tiles.
//   T=64, B=64, H=E=1000, V=10000, 11 edges.
// ---------------------------------------------------------------------------

namespace {

constexpr int Hd = 1000;
constexpr int Bb = 64;
constexpr int Tt = 64;
constexpr int Vv = 10000;

constexpr int BM = 32;     // batch rows per CTA
constexpr int BNt = 16;    // output cols per CTA
constexpr int KT = 40;     // K tile
constexpr int NT = 63;     // ceil(1000/16)

typedef unsigned long long u64;

// Scratch (static device arrays are allowed).
__device__ __align__(256) float g_h[12][Bb * Hd];
__device__ __align__(256) float g_c0[Bb * Hd];
__device__ __align__(256) float g_outs[Tt * Bb * Hd];

__device__ __forceinline__ float sigmf(float x) { return 1.0f / (1.0f + expf(-x)); }

__device__ __forceinline__ float applyAct(int a, float v) {
    switch (a) {
        case 0: return fmaxf(v, 0.0f);
        case 1: return tanhf(v);
        case 2: return sigmf(v);
        default: return v;
    }
}

__device__ __forceinline__ void fma2(u64& d, u64 a, u64 b) {
    asm("fma.rn.f32x2 %0, %1, %2, %0;" : "+l"(d) : "l"(a), "l"(b));
}
__device__ __forceinline__ u64 dup2(float x) {
    u64 r; asm("mov.b64 %0, {%1, %1};" : "=l"(r) : "f"(x)); return r;
}
__device__ __forceinline__ float2 unpk(u64 v) {
    float2 r; asm("mov.b64 {%0, %1}, %2;" : "=f"(r.x), "=f"(r.y) : "l"(v)); return r;
}

struct EdgeDesc { int parent; int child; int w; int act; };
struct LevelDesc { EdgeDesc e[3]; };

// ---------------------------------------------------------------------------
// Generic DAG level. Each CTA: BM=32 x BN=16 tile of one edge's dual GEMM.
// grid = (63 ntiles, 2 mtiles, n_edges), 64 threads.
// h[j] = sigmoid(h[i]@Wc^T) * act(h[i]@Wh^T) + (1-c0)*h[i]
// ---------------------------------------------------------------------------
__global__ __launch_bounds__(64) void level_kernel(
    LevelDesc L, const float* __restrict__ Wh, const float* __restrict__ Wc)
{
    __shared__ __align__(16) float As[2][KT][36];
    __shared__ __align__(16) float Bs[2][2][KT][20];

    const EdgeDesc ed = L.e[blockIdx.z];
    const float* __restrict__ hin = g_h[ed.parent];
    float* __restrict__ hout = g_h[ed.child];
    const float* __restrict__ wmat[2] = {
        Wh + (size_t)ed.w * Hd * Hd, Wc + (size_t)ed.w * Hd * Hd };

    const int tid = threadIdx.x;
    const int m0 = blockIdx.y * BM;
    const int n0 = blockIdx.x * BNt;
    const int bl = (tid >> 3) * 4;
    const int nl = (tid & 7) * 2;

    float4 pa[5], pb[5];

    auto ldg = [&](int k0) {
#pragma unroll
        for (int i = 0; i < 5; i++) {
            int e = i * 64 + tid;
            pa[i] = *reinterpret_cast<const float4*>(
                &hin[(m0 + e / 10) * Hd + k0 + (e % 10) * 4]);
        }
#pragma unroll
        for (int i = 0; i < 5; i++) {
            int e = i * 64 + tid;
            int mat = e / 160, rr = e % 160;
            int gn = n0 + rr / 10;
            pb[i] = (gn < Hd)
                ? *reinterpret_cast<const float4*>(&wmat[mat][(size_t)gn * Hd + k0 + (rr % 10) * 4])
                : make_float4(0.f, 0.f, 0.f, 0.f);
        }
    };
    auto sts = [&](int buf) {
#pragma unroll
        for (int i = 0; i < 5; i++) {
            int e = i * 64 + tid;
            int row = e / 10, kq = (e % 10) * 4;
            As[buf][kq + 0][row] = pa[i].x;
            As[buf][kq + 1][row] = pa[i].y;
            As[buf][kq + 2][row] = pa[i].z;
            As[buf][kq + 3][row] = pa[i].w;
        }
#pragma unroll
        for (int i = 0; i < 5; i++) {
            int e = i * 64 + tid;
            int mat = e / 160, rr = e % 160;
            int n = rr / 10, kq = (rr % 10) * 4;
            Bs[buf][mat][kq + 0][n] = pb[i].x;
            Bs[buf][mat][kq + 1][n] = pb[i].y;
            Bs[buf][mat][kq + 2][n] = pb[i].z;
            Bs[buf][mat][kq + 3][n] = pb[i].w;
        }
    };

    u64 ah[4] = {}, ac[4] = {};

    ldg(0); sts(0); __syncthreads();

    const int NKT = Hd / KT;  // 25
    for (int tile = 0; tile < NKT; ++tile) {
        int cur = tile & 1, nxt = cur ^ 1;
        if (tile + 1 < NKT) ldg((tile + 1) * KT);
#pragma unroll 8
        for (int kk = 0; kk < KT; ++kk) {
            float4 a4 = *reinterpret_cast<const float4*>(&As[cur][kk][bl]);
            u64 bh = *reinterpret_cast<const u64*>(&Bs[cur][0][kk][nl]);
            u64 bc = *reinterpret_cast<const u64*>(&Bs[cur][1][kk][nl]);
            u64 a0 = dup2(a4.x), a1 = dup2(a4.y), a2 = dup2(a4.z), a3 = dup2(a4.w);
            fma2(ah[0], a0, bh); fma2(ac[0], a0, bc);
            fma2(ah[1], a1, bh); fma2(ac[1], a1, bc);
            fma2(ah[2], a2, bh); fma2(ac[2], a2, bc);
            fma2(ah[3], a3, bh); fma2(ac[3], a3, bc);
        }
        if (tile + 1 < NKT) sts(nxt);
        __syncthreads();
    }

#pragma unroll
    for (int i = 0; i < 4; i++) {
        const int b = m0 + bl + i;
        float2 hv = unpk(ah[i]), cv = unpk(ac[i]);
#pragma unroll
        for (int j = 0; j < 2; j++) {
            const int n = n0 + nl + j;
            if (n < Hd) {
                const int idx = b * Hd + n;
                float cj = sigmf(j ? cv.y : cv.x);
                float v = applyAct(ed.act, j ? hv.y : hv.x);
                hout[idx] = cj * v + (1.0f - g_c0[idx]) * hin[idx];
            }
        }
    }
}

// ---------------------------------------------------------------------------
// cell0: K = 2000 (embedding gather || h_prev).
// ---------------------------------------------------------------------------
__global__ __launch_bounds__(64) void cell0_kernel(
    const int* __restrict__ inputs, const float* __restrict__ hinit,
    const float* __restrict__ emb,
    const float* __restrict__ w_xh, const float* __restrict__ b_xh,
    const float* __restrict__ w_xc, const float* __restrict__ b_xc,
    int t)
{
    __shared__ __align__(16) float As[2][KT][36];
    __shared__ __align__(16) float Bs[2][2][KT][20];
    __shared__ int toks[BM];

    const float* __restrict__ hprev = (t == 0) ? hinit : g_h[11];
    const float* __restrict__ wmat[2] = { w_xh, w_xc };

    const int tid = threadIdx.x;
    const int m0 = blockIdx.y * BM;
    const int n0 = blockIdx.x * BNt;
    const int bl = (tid >> 3) * 4;
    const int nl = (tid & 7) * 2;

    if (tid < BM) toks[tid] = inputs[t * Bb + m0 + tid];
    __syncthreads();

    float4 pa[5], pb[5];

    auto ldg = [&](int k0) {
#pragma unroll
        for (int i = 0; i < 5; i++) {
            int e = i * 64 + tid;
            int row = e / 10, kq = (e % 10) * 4;
            if (k0 < Hd)
                pa[i] = *reinterpret_cast<const float4*>(&emb[(size_t)toks[row] * Hd + k0 + kq]);
            else
                pa[i] = *reinterpret_cast<const float4*>(&hprev[(m0 + row) * Hd + (k0 - Hd) + kq]);
        }
#pragma unroll
        for (int i = 0; i < 5; i++) {
            int e = i * 64 + tid;
            int mat = e / 160, rr = e % 160;
            int gn = n0 + rr / 10;
            pb[i] = (gn < Hd)
                ? *reinterpret_cast<const float4*>(&wmat[mat][(size_t)gn * 2 * Hd + k0 + (rr % 10) * 4])
                : make_float4(0.f, 0.f, 0.f, 0.f);
        }
    };
    auto sts = [&](int buf) {
#pragma unroll
        for (int i = 0; i < 5; i++) {
            int e = i * 64 + tid;
            int row = e / 10, kq = (e % 10) * 4;
            As[buf][kq + 0][row] = pa[i].x;
            As[buf][kq + 1][row] = pa[i].y;
            As[buf][kq + 2][row] = pa[i].z;
            As[buf][kq + 3][row] = pa[i].w;
        }
#pragma unroll
        for (int i = 0; i < 5; i++) {
            int e = i * 64 + tid;
            int mat = e / 160, rr = e % 160;
            int n = rr / 10, kq = (rr % 10) * 4;
            Bs[buf][mat][kq + 0][n] = pb[i].x;
            Bs[buf][mat][kq + 1][n] = pb[i].y;
            Bs[buf][mat][kq + 2][n] = pb[i].z;
            Bs[buf][mat][kq + 3][n] = pb[i].w;
        }
    };

    u64 ah[4] = {}, ac[4] = {};

    ldg(0); sts(0); __syncthreads();

    const int NKT = 2 * Hd / KT;  // 50
    for (int tile = 0; tile < NKT; ++tile) {
        int cur = tile & 1, nxt = cur ^ 1;
        if (tile + 1 < NKT) ldg((tile + 1) * KT);
#pragma unroll 8
        for (int kk = 0; kk < KT; ++kk) {
            float4 a4 = *reinterpret_cast<const float4*>(&As[cur][kk][bl]);
            u64 bh = *reinterpret_cast<const u64*>(&Bs[cur][0][kk][nl]);
            u64 bc = *reinterpret_cast<const u64*>(&Bs[cur][1][kk][nl]);
            u64 a0 = dup2(a4.x), a1 = dup2(a4.y), a2 = dup2(a4.z), a3 = dup2(a4.w);
            fma2(ah[0], a0, bh); fma2(ac[0], a0, bc);
            fma2(ah[1], a1, bh); fma2(ac[1], a1, bc);
            fma2(ah[2], a2, bh); fma2(ac[2], a2, bc);
            fma2(ah[3], a3, bh); fma2(ac[3], a3, bc);
        }
        if (tile + 1 < NKT) sts(nxt);
        __syncthreads();
    }

#pragma unroll
    for (int i = 0; i < 4; i++) {
        const int b = m0 + bl + i;
        float2 hv = unpk(ah[i]), cv = unpk(ac[i]);
#pragma unroll
        for (int j = 0; j < 2; j++) {
            const int n = n0 + nl + j;
            if (n < Hd) {
                const int idx = b * Hd + n;
                float c0v = sigmf((j ? cv.y : cv.x) + b_xc[n]);
                float h0 = c0v * tanhf((j ? hv.y : hv.x) + b_xh[n]) + (1.0f - c0v) * hprev[idx];
                g_c0[idx] = c0v;
                g_h[0][idx] = h0;
            }
        }
    }
}

// ---------------------------------------------------------------------------
// Leaf mean: out[t] = (h5+h7+h8+h9+h10+h11)/6
// ---------------------------------------------------------------------------
__global__ __launch_bounds__(256) void mean_kernel(int t) {
    int i = blockIdx.x * 256 + threadIdx.x;
    if (i < Bb * Hd) {
        g_outs[(size_t)t * Bb * Hd + i] =
            (g_h[5][i] + g_h[7][i] + g_h[8][i] + g_h[9][i] + g_h[10][i] + g_h[11][i]) * (1.0f / 6.0f);
    }
}

// ---------------------------------------------------------------------------
// Decoder: [4096 x 10000] = g_outs[4096 x 1000] @ dec_w^T + dec_b.
// 128x128 tile, 256 threads, 8x8 micro with f32x2, double buffered, DKT=20.
// ---------------------------------------------------------------------------
constexpr int DKT = 20;

__global__ __launch_bounds__(256, 1) void decoder_kernel(
    const float* __restrict__ dec_w, const float* __restrict__ dec_b,
    float* __restrict__ out)
{
    __shared__ __align__(16) float As[2][DKT][132];
    __shared__ __align__(16) float Bs[2][DKT][132];

    const int tid = threadIdx.x;
    const int m0 = blockIdx.y * 128;
    const int v0 = blockIdx.x * 128;
    const int ml = (tid >> 4) * 8;
    const int vl = (tid & 15) * 8;

    float4 p[5];

    auto ldg = [&](int k0) {
#pragma unroll
        for (int i = 0; i < 5; i++) {
            int e = i * 256 + tid;
            if (e < 640) {
                int row = e / 5, kq = (e % 5) * 4;
                p[i] = *reinterpret_cast<const float4*>(&g_outs[(size_t)(m0 + row) * Hd + k0 + kq]);
            } else {
                int ee = e - 640;
                int gv = v0 + ee / 5, kq = (ee % 5) * 4;
                p[i] = (gv < Vv)
                    ? *reinterpret_cast<const float4*>(&dec_w[(size_t)gv * Hd + k0 + kq])
                    : make_float4(0.f, 0.f, 0.f, 0.f);
            }
        }
    };
    auto sts = [&](int buf) {
#pragma unroll
        for (int i = 0; i < 5; i++) {
            int e = i * 256 + tid;
            if (e < 640) {
                int row = e / 5, kq = (e % 5) * 4;
                As[buf][kq + 0][row] = p[i].x;
                As[buf][kq + 1][row] = p[i].y;
                As[buf][kq + 2][row] = p[i].z;
                As[buf][kq + 3][row] = p[i].w;
            } else {
                int ee = e - 640;
                int row = ee / 5, kq = (ee % 5) * 4;
                Bs[buf][kq + 0][row] = p[i].x;
                Bs[buf][kq + 1][row] = p[i].y;
                Bs[buf][kq + 2][row] = p[i].z;
                Bs[buf][kq + 3][row] = p[i].w;
            }
        }
    };

    u64 acc[8][4] = {};

    ldg(0); sts(0); __syncthreads();

    const int NKT = Hd / DKT;  // 50
    for (int tile = 0; tile < NKT; ++tile) {
        int cur = tile & 1, nxt = cur ^ 1;
        if (tile + 1 < NKT) ldg((tile + 1) * DKT);
#pragma unroll 4
        for (int kk = 0; kk < DKT; ++kk) {
            float4 a0 = *reinterpret_cast<const float4*>(&As[cur][kk][ml]);
            float4 a1 = *reinterpret_cast<const float4*>(&As[cur][kk][ml + 4]);
            u64 b0 = *reinterpret_cast<const u64*>(&Bs[cur][kk][vl]);
            u64 b1 = *reinterpret_cast<const u64*>(&Bs[cur][kk][vl + 2]);
            u64 b2 = *reinterpret_cast<const u64*>(&Bs[cur][kk][vl + 4]);
            u64 b3 = *reinterpret_cast<const u64*>(&Bs[cur][kk][vl + 6]);
            u64 ad[8] = { dup2(a0.x), dup2(a0.y), dup2(a0.z), dup2(a0.w),
                          dup2(a1.x), dup2(a1.y), dup2(a1.z), dup2(a1.w) };
#pragma unroll
            for (int i = 0; i < 8; i++) {
                fma2(acc[i][0], ad[i], b0);
                fma2(acc[i][1], ad[i], b1);
                fma2(acc[i][2], ad[i], b2);
                fma2(acc[i][3], ad[i], b3);
            }
        }
        if (tile + 1 < NKT) sts(nxt);
        __syncthreads();
    }

#pragma unroll
    for (int i = 0; i < 8; i++) {
        const int m = m0 + ml + i;
#pragma unroll
        for (int j = 0; j < 4; j++) {
            float2 r = unpk(acc[i][j]);
            const int v = v0 + vl + 2 * j;
            if (v < Vv)     out[(size_t)m * Vv + v]     = r.x + dec_b[v];
            if (v + 1 < Vv) out[(size_t)m * Vv + v + 1] = r.y + dec_b[v + 1];
        }
    }
}

} // namespace

// ---------------------------------------------------------------------------
extern "C" void kernel_launch(void* const* d_in, const int* in_sizes, int n_in,
                              void* d_out, int out_size)
{
    (void)in_sizes; (void)n_in; (void)out_size;

    const int*   inputs = (const int*)  d_in[0];
    const float* hidden = (const float*)d_in[1];
    const float* emb    = (const float*)d_in[2];
    const float* w_xh   = (const float*)d_in[3];
    const float* b_xh   = (const float*)d_in[4];
    const float* w_xc   = (const float*)d_in[5];
    const float* b_xc   = (const float*)d_in[6];
    const float* Wh     = (const float*)d_in[7];
    const float* Wc     = (const float*)d_in[8];
    const float* dec_w  = (const float*)d_in[9];
    const float* dec_b  = (const float*)d_in[10];
    float* out = (float*)d_out;

    // acts: 0=relu, 1=tanh, 2=sigmoid, 3=identity
    const LevelDesc LV1 = {{ {0, 1, 0, 0},  {0, 6, 1, 1},  {0, 0, 0, 3} }};
    const LevelDesc LV2 = {{ {1, 2, 2, 0},  {1, 8, 3, 2},  {6, 7, 10, 1} }};
    const LevelDesc LV3 = {{ {2, 3, 4, 1},  {2, 9, 5, 0},  {0, 0, 0, 3} }};
    const LevelDesc LV4 = {{ {3, 4, 6, 3},  {3, 10, 7, 1}, {0, 0, 0, 3} }};
    const LevelDesc LV5 = {{ {4, 5, 8, 0},  {4, 11, 9, 2}, {0, 0, 0, 3} }};

    dim3 blk(64);
    for (int t = 0; t < Tt; ++t) {
        cell0_kernel<<<dim3(NT, 2), blk>>>(inputs, hidden, emb, w_xh, b_xh, w_xc, b_xc, t);
        level_kernel<<<dim3(NT, 2, 2), blk>>>(LV1, Wh, Wc);
        level_kernel<<<dim3(NT, 2, 3), blk>>>(LV2, Wh, Wc);
        level_kernel<<<dim3(NT, 2, 2), blk>>>(LV3, Wh, Wc);
        level_kernel<<<dim3(NT, 2, 2), blk>>>(LV4, Wh, Wc);
        level_kernel<<<dim3(NT, 2, 2), blk>>>(LV5, Wh, Wc);
        mean_kernel<<<(Bb * Hd + 255) / 256, 256>>>(t);
    }

    decoder_kernel<<<dim3((Vv + 127) / 128, (Tt * Bb) / 128), dim3(256)>>>(dec_w, dec_b, out);
}

// round 3
// speedup vs baseline: 6.0917x; 1.6972x over previous
#include <cuda_runtime.h>
#include <cuda_bf16.h>

// ---------------------------------------------------------------------------
// ENAS RNN — round 3: tensor cores (mma.sync bf16) with 3-term hi/lo split
// for fp32-grade accuracy. T=64, B=64, H=E=1000, V=10000.
// ---------------------------------------------------------------------------

namespace {

typedef unsigned int u32;

constexpr int Hd = 1000;
constexpr int Bb = 64;
constexpr int Tt = 64;
constexpr int Vv = 10000;

constexpr int KT = 48;     // k per smem chunk
constexpr int KP = 56;     // smem k pitch (bank-friendly)
constexpr int NCH = 21;    // 21*48 = 1008 >= 1000 (zero padded)

// ---------------- static device storage (no runtime alloc allowed) --------
__device__ __align__(16) __nv_bfloat16 g_Whhi[11000000], g_Whlo[11000000];
__device__ __align__(16) __nv_bfloat16 g_Wchi[11000000], g_Wclo[11000000];
__device__ __align__(16) __nv_bfloat16 g_dechi[10000000], g_declo[10000000];
__device__ __align__(16) __nv_bfloat16 g_embhi[10000000], g_emblo[10000000];
__device__ __align__(16) __nv_bfloat16 g_wxhe_hi[1000000], g_wxhe_lo[1000000];
__device__ __align__(16) __nv_bfloat16 g_wxhh_hi[1000000], g_wxhh_lo[1000000];
__device__ __align__(16) __nv_bfloat16 g_wxce_hi[1000000], g_wxce_lo[1000000];
__device__ __align__(16) __nv_bfloat16 g_wxch_hi[1000000], g_wxch_lo[1000000];

__device__ __align__(16) float g_h[12][Bb * Hd];
__device__ __align__(16) __nv_bfloat16 g_hhi[12][Bb * Hd];
__device__ __align__(16) __nv_bfloat16 g_hlo[12][Bb * Hd];
__device__ __align__(16) float g_c0[Bb * Hd];
__device__ __align__(16) float g_Ph[Tt * Bb * Hd];
__device__ __align__(16) float g_Pc[Tt * Bb * Hd];
__device__ __align__(16) __nv_bfloat16 g_outshi[Tt * Bb * Hd];
__device__ __align__(16) __nv_bfloat16 g_outslo[Tt * Bb * Hd];

// ---------------- helpers --------------------------------------------------
__device__ __forceinline__ float sigmf(float x) { return 1.0f / (1.0f + expf(-x)); }

__device__ __forceinline__ float applyAct(int a, float v) {
    switch (a) {
        case 0: return fmaxf(v, 0.0f);
        case 1: return tanhf(v);
        case 2: return sigmf(v);
        default: return v;
    }
}

__device__ __forceinline__ void split1(float x, __nv_bfloat16& h, __nv_bfloat16& l) {
    h = __float2bfloat16(x);
    l = __float2bfloat16(x - __bfloat162float(h));
}
__device__ __forceinline__ u32 b2u(__nv_bfloat16 a, __nv_bfloat16 b) {
    return (u32)__bfloat16_as_ushort(a) | ((u32)__bfloat16_as_ushort(b) << 16);
}

__device__ __forceinline__ void mma16816(float (&d)[4], const u32 (&a)[4], u32 b0, u32 b1) {
    asm volatile(
        "mma.sync.aligned.m16n8k16.row.col.f32.bf16.bf16.f32 "
        "{%0,%1,%2,%3}, {%4,%5,%6,%7}, {%8,%9}, {%0,%1,%2,%3};"
        : "+f"(d[0]), "+f"(d[1]), "+f"(d[2]), "+f"(d[3])
        : "r"(a[0]), "r"(a[1]), "r"(a[2]), "r"(a[3]), "r"(b0), "r"(b1));
}

struct EdgeDesc { int parent; int child; int w; int act; };
struct LevelDesc { EdgeDesc e[3]; };

// ---------------------------------------------------------------------------
// Core dual GEMM mainloop. A: 64 x 1000 (pre-split bf16 hi/lo, row given by
// rowf). B1/B2: [n][1000] pre-split. CTA covers n-tile of 16 for each of B1,B2
// (32 smem rows). 128 threads = 4 warps; warp w owns m-rows [16w,16w+16).
// acc[j][*]: j=0,1 -> B1 n-blocks (n+0..7, n+8..15); j=2,3 -> B2.
// D = Ahi*Bhi + Ahi*Blo + Alo*Bhi  (fp32 accum).
// ---------------------------------------------------------------------------
template <class ROWF>
__device__ __forceinline__ void dual_mma_main(
    const __nv_bfloat16* __restrict__ Agh, const __nv_bfloat16* __restrict__ Agl,
    ROWF rowf,
    const __nv_bfloat16* __restrict__ B1h, const __nv_bfloat16* __restrict__ B1l, int nb1, int nl1,
    const __nv_bfloat16* __restrict__ B2h, const __nv_bfloat16* __restrict__ B2l, int nb2, int nl2,
    float (&acc)[4][4])
{
    __shared__ __align__(16) __nv_bfloat16 sAh[2][64][KP];
    __shared__ __align__(16) __nv_bfloat16 sAl[2][64][KP];
    __shared__ __align__(16) __nv_bfloat16 sBh[2][32][KP];
    __shared__ __align__(16) __nv_bfloat16 sBl[2][32][KP];

    const int tid = threadIdx.x;
    uint4 pah[3], pal[3];
    uint2 pbh[3], pbl[3];

    auto ldg = [&](int k0) {
#pragma unroll
        for (int i = 0; i < 3; i++) {            // A: 64 rows x 48 bf16, 8/thr
            int e = i * 128 + tid;
            int row = e / 6, kq = (e % 6) * 8;
            int k = k0 + kq;
            if (k + 8 <= Hd) {
                size_t off = (size_t)rowf(row) * Hd + k;
                pah[i] = *(const uint4*)(Agh + off);
                pal[i] = *(const uint4*)(Agl + off);
            } else {
                pah[i] = make_uint4(0, 0, 0, 0);
                pal[i] = make_uint4(0, 0, 0, 0);
            }
        }
#pragma unroll
        for (int i = 0; i < 3; i++) {            // B: 32 rows x 48 bf16, 4/thr
            int e = i * 128 + tid;
            int row = e / 12, kq = (e % 12) * 4;
            int k = k0 + kq;
            const __nv_bfloat16 *bh, *bl;
            int n, nl;
            if (row < 16) { n = nb1 + row;       bh = B1h; bl = B1l; nl = nl1; }
            else          { n = nb2 + row - 16;  bh = B2h; bl = B2l; nl = nl2; }
            if (k + 4 <= Hd && n < nl) {
                size_t off = (size_t)n * Hd + k;
                pbh[i] = *(const uint2*)(bh + off);
                pbl[i] = *(const uint2*)(bl + off);
            } else {
                pbh[i] = make_uint2(0, 0);
                pbl[i] = make_uint2(0, 0);
            }
        }
    };
    auto sts = [&](int buf) {
#pragma unroll
        for (int i = 0; i < 3; i++) {
            int e = i * 128 + tid;
            int row = e / 6, kq = (e % 6) * 8;
            *(uint4*)&sAh[buf][row][kq] = pah[i];
            *(uint4*)&sAl[buf][row][kq] = pal[i];
        }
#pragma unroll
        for (int i = 0; i < 3; i++) {
            int e = i * 128 + tid;
            int row = e / 12, kq = (e % 12) * 4;
            *(uint2*)&sBh[buf][row][kq] = pbh[i];
            *(uint2*)&sBl[buf][row][kq] = pbl[i];
        }
    };

    const int w = tid >> 5, lane = tid & 31;
    const int g = lane >> 2, tq = lane & 3;
    const int ar0 = 16 * w + g;

    ldg(0); sts(0); __syncthreads();

    for (int ch = 0; ch < NCH; ++ch) {
        const int cur = ch & 1;
        if (ch + 1 < NCH) ldg((ch + 1) * KT);
#pragma unroll
        for (int k16 = 0; k16 < 3; k16++) {
            const int kb = k16 * 16 + 2 * tq;
            u32 ah[4], al[4];
            ah[0] = *(const u32*)&sAh[cur][ar0][kb];
            ah[1] = *(const u32*)&sAh[cur][ar0 + 8][kb];
            ah[2] = *(const u32*)&sAh[cur][ar0][kb + 8];
            ah[3] = *(const u32*)&sAh[cur][ar0 + 8][kb + 8];
            al[0] = *(const u32*)&sAl[cur][ar0][kb];
            al[1] = *(const u32*)&sAl[cur][ar0 + 8][kb];
            al[2] = *(const u32*)&sAl[cur][ar0][kb + 8];
            al[3] = *(const u32*)&sAl[cur][ar0 + 8][kb + 8];
#pragma unroll
            for (int j = 0; j < 4; j++) {
                const int br = j * 8 + g;
                u32 bh0 = *(const u32*)&sBh[cur][br][kb];
                u32 bh1 = *(const u32*)&sBh[cur][br][kb + 8];
                u32 bl0 = *(const u32*)&sBl[cur][br][kb];
                u32 bl1 = *(const u32*)&sBl[cur][br][kb + 8];
                mma16816(acc[j], ah, bh0, bh1);
                mma16816(acc[j], ah, bl0, bl1);
                mma16816(acc[j], al, bh0, bh1);
            }
        }
        if (ch + 1 < NCH) sts((ch + 1) & 1);
        __syncthreads();
    }
}

// ---------------------------------------------------------------------------
// prep: split all static operands into bf16 hi/lo.
// Unit segments: Wh(2.75M f4) Wc(2.75M) dec(2.5M) emb(2.5M) hidden(16K)
//                wxh(250K strided) wxc(250K strided)
// ---------------------------------------------------------------------------
constexpr int S0 = 2750000;            // Wh
constexpr int S1 = S0 + 2750000;       // Wc
constexpr int S2 = S1 + 2500000;       // dec
constexpr int S3 = S2 + 2500000;       // emb
constexpr int S4 = S3 + 16000;         // hidden
constexpr int S5 = S4 + 250000;        // wxh
constexpr int S6 = S5 + 250000;        // wxc
constexpr int PREP_UNITS = S6;

__device__ __forceinline__ void split4_store(float4 v, __nv_bfloat16* hi, __nv_bfloat16* lo, size_t o) {
    __nv_bfloat16 h0, l0, h1, l1, h2, l2, h3, l3;
    split1(v.x, h0, l0); split1(v.y, h1, l1); split1(v.z, h2, l2); split1(v.w, h3, l3);
    *(uint2*)&hi[o] = make_uint2(b2u(h0, h1), b2u(h2, h3));
    *(uint2*)&lo[o] = make_uint2(b2u(l0, l1), b2u(l2, l3));
}

__global__ __launch_bounds__(256) void prep_split(
    const float* __restrict__ Wh, const float* __restrict__ Wc,
    const float* __restrict__ dec_w, const float* __restrict__ emb,
    const float* __restrict__ hidden,
    const float* __restrict__ w_xh, const float* __restrict__ w_xc)
{
    int i = blockIdx.x * 256 + threadIdx.x;
    if (i >= PREP_UNITS) return;
    if (i < S0) {
        split4_store(*((const float4*)Wh + i), g_Whhi, g_Whlo, (size_t)i * 4);
    } else if (i < S1) {
        int j = i - S0;
        split4_store(*((const float4*)Wc + j), g_Wchi, g_Wclo, (size_t)j * 4);
    } else if (i < S2) {
        int j = i - S1;
        split4_store(*((const float4*)dec_w + j), g_dechi, g_declo, (size_t)j * 4);
    } else if (i < S3) {
        int j = i - S2;
        split4_store(*((const float4*)emb + j), g_embhi, g_emblo, (size_t)j * 4);
    } else if (i < S4) {
        int j = i - S3;
        split4_store(*((const float4*)hidden + j), g_hhi[11], g_hlo[11], (size_t)j * 4);
    } else if (i < S5) {
        int j = i - S4;
        int row = j / 250, kq = (j % 250) * 4;
        split4_store(*(const float4*)(w_xh + (size_t)row * 2000 + kq),       g_wxhe_hi, g_wxhe_lo, (size_t)row * Hd + kq);
        split4_store(*(const float4*)(w_xh + (size_t)row * 2000 + 1000 + kq), g_wxhh_hi, g_wxhh_lo, (size_t)row * Hd + kq);
    } else {
        int j = i - S5;
        int row = j / 250, kq = (j % 250) * 4;
        split4_store(*(const float4*)(w_xc + (size_t)row * 2000 + kq),       g_wxce_hi, g_wxce_lo, (size_t)row * Hd + kq);
        split4_store(*(const float4*)(w_xc + (size_t)row * 2000 + 1000 + kq), g_wxch_hi, g_wxch_lo, (size_t)row * Hd + kq);
    }
}

// ---------------------------------------------------------------------------
// Precompute P = gather(emb) @ w_x{h,c}_embpart^T + bias for all T*B tokens.
// grid = (63 ntiles, 64 mtiles), 128 threads.
// ---------------------------------------------------------------------------
__global__ __launch_bounds__(128) void precomp_mma(
    const int* __restrict__ inputs,
    const float* __restrict__ b_xh, const float* __restrict__ b_xc)
{
    __shared__ int toks[64];
    const int m0 = blockIdx.y * 64;
    if (threadIdx.x < 64) toks[threadIdx.x] = inputs[m0 + threadIdx.x];
    __syncthreads();

    const int n0 = blockIdx.x * 16;
    float acc[4][4] = {};
    dual_mma_main(g_embhi, g_emblo, [&](int m) { return toks[m]; },
                  g_wxhe_hi, g_wxhe_lo, n0, Hd,
                  g_wxce_hi, g_wxce_lo, n0, Hd, acc);

    const int w = threadIdx.x >> 5, lane = threadIdx.x & 31;
    const int g = lane >> 2, tq = lane & 3;
#pragma unroll
    for (int jn = 0; jn < 2; jn++)
#pragma unroll
        for (int r = 0; r < 2; r++) {
            const int m = m0 + 16 * w + g + 8 * r;
            const int n = n0 + jn * 8 + 2 * tq;
            if (n < Hd) {
                const size_t idx = (size_t)m * Hd + n;
                float2 bh = *(const float2*)&b_xh[n];
                float2 bc = *(const float2*)&b_xc[n];
                *(float2*)&g_Ph[idx] = make_float2(acc[jn][2 * r] + bh.x, acc[jn][2 * r + 1] + bh.y);
                *(float2*)&g_Pc[idx] = make_float2(acc[2 + jn][2 * r] + bc.x, acc[2 + jn][2 * r + 1] + bc.y);
            }
        }
}

// ---------------------------------------------------------------------------
// cell0: h-part GEMM (K=1000) + precomputed emb part.
// ---------------------------------------------------------------------------
__global__ __launch_bounds__(128) void cell0_mma(const float* __restrict__ hidden, int t)
{
    const float* __restrict__ hprev = (t == 0) ? hidden : g_h[11];
    const int n0 = blockIdx.x * 16;
    float acc[4][4] = {};
    dual_mma_main(g_hhi[11], g_hlo[11], [](int m) { return m; },
                  g_wxhh_hi, g_wxhh_lo, n0, Hd,
                  g_wxch_hi, g_wxch_lo, n0, Hd, acc);

    const int w = threadIdx.x >> 5, lane = threadIdx.x & 31;
    const int g = lane >> 2, tq = lane & 3;
#pragma unroll
    for (int jn = 0; jn < 2; jn++)
#pragma unroll
        for (int r = 0; r < 2; r++) {
            const int m = 16 * w + g + 8 * r;
            const int n = n0 + jn * 8 + 2 * tq;
            if (n < Hd) {
                const int idx = m * Hd + n;
                const size_t pidx = (size_t)(t * Bb + m) * Hd + n;
                float2 ph = *(const float2*)&g_Ph[pidx];
                float2 pc = *(const float2*)&g_Pc[pidx];
                float2 hp = *(const float2*)&hprev[idx];
                float c0a = sigmf(acc[2 + jn][2 * r] + pc.x);
                float c0b = sigmf(acc[2 + jn][2 * r + 1] + pc.y);
                float h0a = c0a * tanhf(acc[jn][2 * r] + ph.x) + (1.0f - c0a) * hp.x;
                float h0b = c0b * tanhf(acc[jn][2 * r + 1] + ph.y) + (1.0f - c0b) * hp.y;
                *(float2*)&g_c0[idx] = make_float2(c0a, c0b);
                *(float2*)&g_h[0][idx] = make_float2(h0a, h0b);
                __nv_bfloat16 ha, la, hb, lb;
                split1(h0a, ha, la); split1(h0b, hb, lb);
                *(u32*)&g_hhi[0][idx] = b2u(ha, hb);
                *(u32*)&g_hlo[0][idx] = b2u(la, lb);
            }
        }
}

// ---------------------------------------------------------------------------
// Generic DAG level. grid = (63, n_edges).
// h[j] = sigmoid(h[i]@Wc^T) * act(h[i]@Wh^T) + (1-c0)*h[i]
// ---------------------------------------------------------------------------
__global__ __launch_bounds__(128) void level_mma(LevelDesc L)
{
    const EdgeDesc ed = L.e[blockIdx.y];
    const float* __restrict__ hin = g_h[ed.parent];
    float* __restrict__ hout = g_h[ed.child];
    const size_t wo = (size_t)ed.w * 1000000;
    const int n0 = blockIdx.x * 16;

    float acc[4][4] = {};
    dual_mma_main(g_hhi[ed.parent], g_hlo[ed.parent], [](int m) { return m; },
                  g_Whhi + wo, g_Whlo + wo, n0, Hd,
                  g_Wchi + wo, g_Wclo + wo, n0, Hd, acc);

    const int w = threadIdx.x >> 5, lane = threadIdx.x & 31;
    const int g = lane >> 2, tq = lane & 3;
#pragma unroll
    for (int jn = 0; jn < 2; jn++)
#pragma unroll
        for (int r = 0; r < 2; r++) {
            const int m = 16 * w + g + 8 * r;
            const int n = n0 + jn * 8 + 2 * tq;
            if (n < Hd) {
                const int idx = m * Hd + n;
                float2 hi2 = *(const float2*)&hin[idx];
                float2 c02 = *(const float2*)&g_c0[idx];
                float oa = sigmf(acc[2 + jn][2 * r]) * applyAct(ed.act, acc[jn][2 * r])
                           + (1.0f - c02.x) * hi2.x;
                float ob = sigmf(acc[2 + jn][2 * r + 1]) * applyAct(ed.act, acc[jn][2 * r + 1])
                           + (1.0f - c02.y) * hi2.y;
                *(float2*)&hout[idx] = make_float2(oa, ob);
                __nv_bfloat16 ha, la, hb, lb;
                split1(oa, ha, la); split1(ob, hb, lb);
                *(u32*)&g_hhi[ed.child][idx] = b2u(ha, hb);
                *(u32*)&g_hlo[ed.child][idx] = b2u(la, lb);
            }
        }
}

// ---------------------------------------------------------------------------
// Leaf mean -> split g_outs
// ---------------------------------------------------------------------------
__global__ __launch_bounds__(256) void mean_kernel(int t)
{
    int i = blockIdx.x * 256 + threadIdx.x;
    if (i < Bb * Hd / 2) {
        int idx = 2 * i;
        float s0 = (g_h[5][idx] + g_h[7][idx] + g_h[8][idx] + g_h[9][idx] + g_h[10][idx] + g_h[11][idx]) * (1.0f / 6.0f);
        float s1 = (g_h[5][idx + 1] + g_h[7][idx + 1] + g_h[8][idx + 1] + g_h[9][idx + 1] + g_h[10][idx + 1] + g_h[11][idx + 1]) * (1.0f / 6.0f);
        __nv_bfloat16 h0, l0, h1, l1;
        split1(s0, h0, l0); split1(s1, h1, l1);
        size_t o = (size_t)t * Bb * Hd + idx;
        *(u32*)&g_outshi[o] = b2u(h0, h1);
        *(u32*)&g_outslo[o] = b2u(l0, l1);
    }
}

// ---------------------------------------------------------------------------
// Decoder: out[m][v] = g_outs[m] . dec_w[v] + dec_b[v].
// Dual machinery covers 32 n per CTA (two 16-row halves of dec_w).
// grid = (313, 64).
// ---------------------------------------------------------------------------
__global__ __launch_bounds__(128) void decoder_mma(
    const float* __restrict__ dec_b, float* __restrict__ out)
{
    const int n0 = blockIdx.x * 32;
    const int m0 = blockIdx.y * 64;
    float acc[4][4] = {};
    dual_mma_main(g_outshi, g_outslo, [&](int m) { return m0 + m; },
                  g_dechi, g_declo, n0, Vv,
                  g_dechi, g_declo, n0 + 16, Vv, acc);

    const int w = threadIdx.x >> 5, lane = threadIdx.x & 31;
    const int g = lane >> 2, tq = lane & 3;
#pragma unroll
    for (int j = 0; j < 4; j++)
#pragma unroll
        for (int r = 0; r < 2; r++) {
            const int m = m0 + 16 * w + g + 8 * r;
            const int n = n0 + (j >> 1) * 16 + (j & 1) * 8 + 2 * tq;
            if (n < Vv) {
                float2 db = *(const float2*)&dec_b[n];
                *(float2*)&out[(size_t)m * Vv + n] =
                    make_float2(acc[j][2 * r] + db.x, acc[j][2 * r + 1] + db.y);
            }
        }
}

} // namespace

// ---------------------------------------------------------------------------
extern "C" void kernel_launch(void* const* d_in, const int* in_sizes, int n_in,
                              void* d_out, int out_size)
{
    (void)in_sizes; (void)n_in; (void)out_size;

    const int*   inputs = (const int*)  d_in[0];
    const float* hidden = (const float*)d_in[1];
    const float* emb    = (const float*)d_in[2];
    const float* w_xh   = (const float*)d_in[3];
    const float* b_xh   = (const float*)d_in[4];
    const float* w_xc   = (const float*)d_in[5];
    const float* b_xc   = (const float*)d_in[6];
    const float* Wh     = (const float*)d_in[7];
    const float* Wc     = (const float*)d_in[8];
    const float* dec_w  = (const float*)d_in[9];
    const float* dec_b  = (const float*)d_in[10];
    float* out = (float*)d_out;

    // acts: 0=relu, 1=tanh, 2=sigmoid, 3=identity
    const LevelDesc LV1 = {{ {0, 1, 0, 0},  {0, 6, 1, 1},  {0, 0, 0, 3} }};
    const LevelDesc LV2 = {{ {1, 2, 2, 0},  {1, 8, 3, 2},  {6, 7, 10, 1} }};
    const LevelDesc LV3 = {{ {2, 3, 4, 1},  {2, 9, 5, 0},  {0, 0, 0, 3} }};
    const LevelDesc LV4 = {{ {3, 4, 6, 3},  {3, 10, 7, 1}, {0, 0, 0, 3} }};
    const LevelDesc LV5 = {{ {4, 5, 8, 0},  {4, 11, 9, 2}, {0, 0, 0, 3} }};

    prep_split<<<(PREP_UNITS + 255) / 256, 256>>>(Wh, Wc, dec_w, emb, hidden, w_xh, w_xc);
    precomp_mma<<<dim3(63, 64), 128>>>(inputs, b_xh, b_xc);

    for (int t = 0; t < Tt; ++t) {
        cell0_mma<<<63, 128>>>(hidden, t);
        level_mma<<<dim3(63, 2), 128>>>(LV1);
        level_mma<<<dim3(63, 3), 128>>>(LV2);
        level_mma<<<dim3(63, 2), 128>>>(LV3);
        level_mma<<<dim3(63, 2), 128>>>(LV4);
        level_mma<<<dim3(63, 2), 128>>>(LV5);
        mean_kernel<<<(Bb * Hd / 2 + 255) / 256, 256>>>(t);
    }

    decoder_mma<<<dim3((Vv + 31) / 32, Tt * Bb / 64), 128>>>(dec_b, out);
}

// round 5
// speedup vs baseline: 8.2672x; 1.3571x over previous
#include <cuda_runtime.h>
#include <cuda_bf16.h>

// ---------------------------------------------------------------------------
// ENAS RNN — round 5: round-4 pipeline with the cp.async drain bug fixed
// (empty commit_group keeps wait_group(S-2) invariant valid on tail chunks).
// mma.sync bf16 3-term split + cp.async 4-stage pipeline + ldmatrix +
// padded K=1024 operands + fused last level/mean.
// ---------------------------------------------------------------------------

namespace {

typedef unsigned int u32;
typedef __nv_bfloat16 bf16;

constexpr int Hd = 1000;
constexpr int Bb = 64;
constexpr int Tt = 64;
constexpr int Vv = 10000;

constexpr int KP = 1024;          // padded K pitch (elements)
constexpr int S = 4;              // pipeline stages
constexpr int KC = 32;            // k per chunk
constexpr int NCHUNK = KP / KC;   // 32

// ---------------- static device storage (zero-initialized at load) ---------
__device__ bf16 g_Whhi[11 * 1000 * KP], g_Whlo[11 * 1000 * KP];
__device__ bf16 g_Wchi[11 * 1000 * KP], g_Wclo[11 * 1000 * KP];
__device__ bf16 g_dechi[10000 * KP], g_declo[10000 * KP];
__device__ bf16 g_embhi[10000 * KP], g_emblo[10000 * KP];
__device__ bf16 g_wxhe_hi[1000 * KP], g_wxhe_lo[1000 * KP];
__device__ bf16 g_wxhh_hi[1000 * KP], g_wxhh_lo[1000 * KP];
__device__ bf16 g_wxce_hi[1000 * KP], g_wxce_lo[1000 * KP];
__device__ bf16 g_wxch_hi[1000 * KP], g_wxch_lo[1000 * KP];

__device__ float g_h[12][Bb * Hd];
__device__ bf16  g_hhi[12][Bb * KP];
__device__ bf16  g_hlo[12][Bb * KP];
__device__ float g_c0[Bb * Hd];
__device__ float g_Ph[Tt * Bb * Hd];
__device__ float g_Pc[Tt * Bb * Hd];
__device__ bf16  g_outshi[Tt * Bb * KP];
__device__ bf16  g_outslo[Tt * Bb * KP];

// ---------------- helpers ---------------------------------------------------
__device__ __forceinline__ float sigmf(float x) { return 1.0f / (1.0f + expf(-x)); }

__device__ __forceinline__ float applyAct(int a, float v) {
    switch (a) {
        case 0: return fmaxf(v, 0.0f);
        case 1: return tanhf(v);
        case 2: return sigmf(v);
        default: return v;
    }
}

__device__ __forceinline__ void split1(float x, bf16& h, bf16& l) {
    h = __float2bfloat16(x);
    l = __float2bfloat16(x - __bfloat162float(h));
}
__device__ __forceinline__ u32 b2u(bf16 a, bf16 b) {
    return (u32)__bfloat16_as_ushort(a) | ((u32)__bfloat16_as_ushort(b) << 16);
}

__device__ __forceinline__ void mma16816(float (&d)[4], const u32 (&a)[4], u32 b0, u32 b1) {
    asm volatile(
        "mma.sync.aligned.m16n8k16.row.col.f32.bf16.bf16.f32 "
        "{%0,%1,%2,%3}, {%4,%5,%6,%7}, {%8,%9}, {%0,%1,%2,%3};"
        : "+f"(d[0]), "+f"(d[1]), "+f"(d[2]), "+f"(d[3])
        : "r"(a[0]), "r"(a[1]), "r"(a[2]), "r"(a[3]), "r"(b0), "r"(b1));
}
__device__ __forceinline__ void ldmA(u32 a, u32 (&r)[4]) {
    asm volatile("ldmatrix.sync.aligned.m8n8.x4.shared.b16 {%0,%1,%2,%3}, [%4];"
                 : "=r"(r[0]), "=r"(r[1]), "=r"(r[2]), "=r"(r[3]) : "r"(a));
}
__device__ __forceinline__ void ldmB(u32 a, u32& b0, u32& b1) {
    asm volatile("ldmatrix.sync.aligned.m8n8.x2.shared.b16 {%0,%1}, [%2];"
                 : "=r"(b0), "=r"(b1) : "r"(a));
}
__device__ __forceinline__ void cpa16(u32 dst, const void* src) {
    asm volatile("cp.async.cg.shared.global [%0], [%1], 16;" :: "r"(dst), "l"(src));
}
__device__ __forceinline__ void cp_commit() { asm volatile("cp.async.commit_group;"); }

struct BPtr { const bf16* hi; const bf16* lo; };
struct EdgeDesc { int parent; int child; int w; int act; int split; };
struct LevelDesc { EdgeDesc e[3]; };

// ---------------------------------------------------------------------------
// Pipelined dual/quad GEMM mainloop. A: 64 x KP bf16 hi/lo (row via arow).
// B: NB groups of 16 rows (bsrc resolves a group-row to hi/lo pointers,
// clamped). 128 threads = 4 warps, warp w owns m [16w,16w+16).
// acc[j] = n-block j of 8 cols (j group-major: group = j>>1).
// D = Ahi*Bhi + Ahi*Blo + Alo*Bhi (fp32 accum).
// smem stage layout: [Ahi 64x40 | Alo | Bhi NB*16x40 | Blo], pitch 40 bf16.
//
// Pipeline invariant: entering iteration ch, exactly ch+3 commit-groups have
// been committed (empty groups at the tail), so wait_group(S-2=2) proves
// group ch complete.
// ---------------------------------------------------------------------------
template <int NB, class AROW, class BSRC>
__device__ __forceinline__ void run_pipeline(
    char* smem, const bf16* __restrict__ Ah, const bf16* __restrict__ Al,
    AROW arow, BSRC bsrc, float (&acc)[2 * NB][4])
{
    constexpr int AHI = 0, ALO = 5120, BHI = 10240, BLO = 10240 + NB * 1280;
    constexpr int SS = 10240 + 2 * NB * 1280;
    constexpr int BCNT = NB / 2;   // B cp.async vectors per thread per precision

    const int tid = threadIdx.x;
    const u32 sbase = (u32)__cvta_generic_to_shared(smem);

    // per-thread cp.async sources/dests (A: 2 x 16B per precision)
    const size_t aoff0 = (size_t)arow(tid >> 2) * KP + (tid & 3) * 8;
    const size_t aoff1 = (size_t)arow((tid + 128) >> 2) * KP + (tid & 3) * 8;
    const u32 adst0 = (u32)((tid >> 2) * 80 + (tid & 3) * 16);
    const u32 adst1 = (u32)(((tid + 128) >> 2) * 80 + (tid & 3) * 16);

    const bf16* bhiP[BCNT];
    const bf16* bloP[BCNT];
    u32 bdst[BCNT];
#pragma unroll
    for (int i = 0; i < BCNT; i++) {
        int e = tid + i * 128;
        BPtr p = bsrc(e >> 2);
        bhiP[i] = p.hi + (e & 3) * 8;
        bloP[i] = p.lo + (e & 3) * 8;
        bdst[i] = (u32)((e >> 2) * 80 + (e & 3) * 16);
    }

    auto issue = [&](int ch) {
        const u32 st = sbase + (u32)((ch & (S - 1)) * SS);
        const int k0 = ch * KC;
        cpa16(st + AHI + adst0, Ah + aoff0 + k0);
        cpa16(st + AHI + adst1, Ah + aoff1 + k0);
        cpa16(st + ALO + adst0, Al + aoff0 + k0);
        cpa16(st + ALO + adst1, Al + aoff1 + k0);
#pragma unroll
        for (int i = 0; i < BCNT; i++) {
            cpa16(st + BHI + bdst[i], bhiP[i] + k0);
            cpa16(st + BLO + bdst[i], bloP[i] + k0);
        }
        cp_commit();
    };

    // fragment lane addresses
    const int lane = tid & 31, w = tid >> 5;
    const int qq = lane >> 3, rr = lane & 7;
    const u32 aAddr = (u32)((16 * w + ((qq & 1) ? 8 : 0) + rr) * 80 + ((qq & 2) ? 16 : 0));
    const u32 bAddr = (u32)(rr * 80 + ((qq & 1) ? 16 : 0));

    issue(0); issue(1); issue(2);

    for (int ch = 0; ch < NCHUNK; ++ch) {
        asm volatile("cp.async.wait_group %0;" :: "n"(S - 2));
        __syncthreads();
        const u32 st = sbase + (u32)((ch & (S - 1)) * SS);
#pragma unroll
        for (int k16 = 0; k16 < KC / 16; k16++) {
            const u32 ko = (u32)(k16 * 32);  // bytes
            u32 ah[4], al[4];
            ldmA(st + AHI + aAddr + ko, ah);
            ldmA(st + ALO + aAddr + ko, al);
#pragma unroll
            for (int j = 0; j < 2 * NB; j++) {
                u32 bh0, bh1, bl0, bl1;
                ldmB(st + BHI + (u32)(j * 640) + bAddr + ko, bh0, bh1);
                ldmB(st + BLO + (u32)(j * 640) + bAddr + ko, bl0, bl1);
                mma16816(acc[j], ah, bh0, bh1);
                mma16816(acc[j], ah, bl0, bl1);
                mma16816(acc[j], al, bh0, bh1);
            }
        }
        // FIX (round 5): keep the committed-group count at ch+3 even when
        // there is nothing left to prefetch — an empty commit_group completes
        // immediately, so wait_group(2) above still proves chunk ch arrived
        // for the tail iterations (the round-4 bug read stale k=960..1023).
        if (ch + 3 < NCHUNK) issue(ch + 3);
        else cp_commit();
        __syncthreads();
    }
}

constexpr int SMEM_NB2 = (10240 + 2 * 2 * 1280) * S;   // 61440
constexpr int SMEM_NB4 = (10240 + 2 * 4 * 1280) * S;   // 81920

// ---------------------------------------------------------------------------
// prep: split all static fp32 operands into bf16 hi/lo with padded pitch.
// Unit = (row, quad-of-4-cols), cols < 1000 only (pads stay zero-init).
// ---------------------------------------------------------------------------
constexpr int U_W = 11000 * 250;
constexpr int U_DEC = 10000 * 250;
constexpr int U_EMB = 10000 * 250;
constexpr int U_HID = 64 * 250;
constexpr int U_WX = 1000 * 250;
constexpr int P0 = U_W;            // Wh
constexpr int P1 = P0 + U_W;       // Wc
constexpr int P2 = P1 + U_DEC;     // dec
constexpr int P3 = P2 + U_EMB;     // emb
constexpr int P4 = P3 + U_HID;     // hidden -> h[11] split
constexpr int P5 = P4 + U_WX;      // w_xh (both halves)
constexpr int P6 = P5 + U_WX;      // w_xc
constexpr int PREP_UNITS = P6;

__device__ __forceinline__ void split4_store(float4 v, bf16* hi, bf16* lo, size_t o) {
    bf16 h0, l0, h1, l1, h2, l2, h3, l3;
    split1(v.x, h0, l0); split1(v.y, h1, l1); split1(v.z, h2, l2); split1(v.w, h3, l3);
    *(uint2*)&hi[o] = make_uint2(b2u(h0, h1), b2u(h2, h3));
    *(uint2*)&lo[o] = make_uint2(b2u(l0, l1), b2u(l2, l3));
}

__global__ __launch_bounds__(256) void prep_split(
    const float* __restrict__ Wh, const float* __restrict__ Wc,
    const float* __restrict__ dec_w, const float* __restrict__ emb,
    const float* __restrict__ hidden,
    const float* __restrict__ w_xh, const float* __restrict__ w_xc)
{
    int i = blockIdx.x * 256 + threadIdx.x;
    if (i >= PREP_UNITS) return;
    if (i < P0) {
        int row = i / 250, col = (i % 250) * 4;
        split4_store(*(const float4*)(Wh + (size_t)row * 1000 + col),
                     g_Whhi, g_Whlo, (size_t)row * KP + col);
    } else if (i < P1) {
        int j = i - P0; int row = j / 250, col = (j % 250) * 4;
        split4_store(*(const float4*)(Wc + (size_t)row * 1000 + col),
                     g_Wchi, g_Wclo, (size_t)row * KP + col);
    } else if (i < P2) {
        int j = i - P1; int row = j / 250, col = (j % 250) * 4;
        split4_store(*(const float4*)(dec_w + (size_t)row * 1000 + col),
                     g_dechi, g_declo, (size_t)row * KP + col);
    } else if (i < P3) {
        int j = i - P2; int row = j / 250, col = (j % 250) * 4;
        split4_store(*(const float4*)(emb + (size_t)row * 1000 + col),
                     g_embhi, g_emblo, (size_t)row * KP + col);
    } else if (i < P4) {
        int j = i - P3; int row = j / 250, col = (j % 250) * 4;
        split4_store(*(const float4*)(hidden + (size_t)row * 1000 + col),
                     g_hhi[11], g_hlo[11], (size_t)row * KP + col);
    } else if (i < P5) {
        int j = i - P4; int row = j / 250, col = (j % 250) * 4;
        split4_store(*(const float4*)(w_xh + (size_t)row * 2000 + col),
                     g_wxhe_hi, g_wxhe_lo, (size_t)row * KP + col);
        split4_store(*(const float4*)(w_xh + (size_t)row * 2000 + 1000 + col),
                     g_wxhh_hi, g_wxhh_lo, (size_t)row * KP + col);
    } else {
        int j = i - P5; int row = j / 250, col = (j % 250) * 4;
        split4_store(*(const float4*)(w_xc + (size_t)row * 2000 + col),
                     g_wxce_hi, g_wxce_lo, (size_t)row * KP + col);
        split4_store(*(const float4*)(w_xc + (size_t)row * 2000 + 1000 + col),
                     g_wxch_hi, g_wxch_lo, (size_t)row * KP + col);
    }
}

// ---------------------------------------------------------------------------
// precomp: P{h,c} = gather(emb) @ w_x{h,c}_embpart^T + bias for all T*B rows.
// ---------------------------------------------------------------------------
__global__ __launch_bounds__(128) void precomp_mma(
    const int* __restrict__ inputs,
    const float* __restrict__ b_xh, const float* __restrict__ b_xc)
{
    extern __shared__ char smem[];
    __shared__ int toks[64];
    const int m0 = blockIdx.y * 64;
    if (threadIdx.x < 64) toks[threadIdx.x] = inputs[m0 + threadIdx.x];
    __syncthreads();

    const int n0 = blockIdx.x * 16;
    float acc[4][4] = {};
    run_pipeline<2>(smem, g_embhi, g_emblo,
        [&](int m) { return toks[m]; },
        [&](int row) {
            int n = min(n0 + (row & 15), Hd - 1);
            return (row < 16)
                ? BPtr{ g_wxhe_hi + (size_t)n * KP, g_wxhe_lo + (size_t)n * KP }
                : BPtr{ g_wxce_hi + (size_t)n * KP, g_wxce_lo + (size_t)n * KP };
        }, acc);

    const int w = threadIdx.x >> 5, lane = threadIdx.x & 31;
    const int g = lane >> 2, tq = lane & 3;
#pragma unroll
    for (int jn = 0; jn < 2; jn++)
#pragma unroll
        for (int r = 0; r < 2; r++) {
            const int m = m0 + 16 * w + g + 8 * r;
            const int n = n0 + jn * 8 + 2 * tq;
            if (n < Hd) {
                const size_t idx = (size_t)m * Hd + n;
                float2 bh = *(const float2*)&b_xh[n];
                float2 bc = *(const float2*)&b_xc[n];
                *(float2*)&g_Ph[idx] = make_float2(acc[jn][2 * r] + bh.x, acc[jn][2 * r + 1] + bh.y);
                *(float2*)&g_Pc[idx] = make_float2(acc[2 + jn][2 * r] + bc.x, acc[2 + jn][2 * r + 1] + bc.y);
            }
        }
}

// ---------------------------------------------------------------------------
// cell0: dual GEMM vs h_prev (K=1000) + precomputed emb part.
// ---------------------------------------------------------------------------
__global__ __launch_bounds__(128) void cell0_mma(const float* __restrict__ hidden, int t)
{
    extern __shared__ char smem[];
    const float* __restrict__ hprev = (t == 0) ? hidden : g_h[11];
    const int n0 = blockIdx.x * 16;
    float acc[4][4] = {};
    run_pipeline<2>(smem, g_hhi[11], g_hlo[11],
        [](int m) { return m; },
        [&](int row) {
            int n = min(n0 + (row & 15), Hd - 1);
            return (row < 16)
                ? BPtr{ g_wxhh_hi + (size_t)n * KP, g_wxhh_lo + (size_t)n * KP }
                : BPtr{ g_wxch_hi + (size_t)n * KP, g_wxch_lo + (size_t)n * KP };
        }, acc);

    const int w = threadIdx.x >> 5, lane = threadIdx.x & 31;
    const int g = lane >> 2, tq = lane & 3;
#pragma unroll
    for (int jn = 0; jn < 2; jn++)
#pragma unroll
        for (int r = 0; r < 2; r++) {
            const int m = 16 * w + g + 8 * r;
            const int n = n0 + jn * 8 + 2 * tq;
            if (n < Hd) {
                const int idx = m * Hd + n;
                const size_t pidx = (size_t)(t * Bb + m) * Hd + n;
                float2 ph = *(const float2*)&g_Ph[pidx];
                float2 pc = *(const float2*)&g_Pc[pidx];
                float2 hp = *(const float2*)&hprev[idx];
                float c0a = sigmf(acc[2 + jn][2 * r] + pc.x);
                float c0b = sigmf(acc[2 + jn][2 * r + 1] + pc.y);
                float h0a = c0a * tanhf(acc[jn][2 * r] + ph.x) + (1.0f - c0a) * hp.x;
                float h0b = c0b * tanhf(acc[jn][2 * r + 1] + ph.y) + (1.0f - c0b) * hp.y;
                *(float2*)&g_c0[idx] = make_float2(c0a, c0b);
                *(float2*)&g_h[0][idx] = make_float2(h0a, h0b);
                bf16 ha, la, hb, lb;
                split1(h0a, ha, la); split1(h0b, hb, lb);
                const size_t sidx = (size_t)m * KP + n;
                *(u32*)&g_hhi[0][sidx] = b2u(ha, hb);
                *(u32*)&g_hlo[0][sidx] = b2u(la, lb);
            }
        }
}

// ---------------------------------------------------------------------------
// Generic DAG level. grid = (63, n_edges).
// ---------------------------------------------------------------------------
__global__ __launch_bounds__(128) void level_mma(LevelDesc L)
{
    extern __shared__ char smem[];
    const EdgeDesc ed = L.e[blockIdx.y];
    const float* __restrict__ hin = g_h[ed.parent];
    float* __restrict__ hout = g_h[ed.child];
    const bf16* whh = g_Whhi + (size_t)ed.w * 1000 * KP;
    const bf16* whl = g_Whlo + (size_t)ed.w * 1000 * KP;
    const bf16* wch = g_Wchi + (size_t)ed.w * 1000 * KP;
    const bf16* wcl = g_Wclo + (size_t)ed.w * 1000 * KP;
    const int n0 = blockIdx.x * 16;

    float acc[4][4] = {};
    run_pipeline<2>(smem, g_hhi[ed.parent], g_hlo[ed.parent],
        [](int m) { return m; },
        [&](int row) {
            size_t n = (size_t)min(n0 + (row & 15), Hd - 1) * KP;
            return (row < 16) ? BPtr{ whh + n, whl + n } : BPtr{ wch + n, wcl + n };
        }, acc);

    const int w = threadIdx.x >> 5, lane = threadIdx.x & 31;
    const int g = lane >> 2, tq = lane & 3;
#pragma unroll
    for (int jn = 0; jn < 2; jn++)
#pragma unroll
        for (int r = 0; r < 2; r++) {
            const int m = 16 * w + g + 8 * r;
            const int n = n0 + jn * 8 + 2 * tq;
            if (n < Hd) {
                const int idx = m * Hd + n;
                float2 hi2 = *(const float2*)&hin[idx];
                float2 c02 = *(const float2*)&g_c0[idx];
                float oa = sigmf(acc[2 + jn][2 * r]) * applyAct(ed.act, acc[jn][2 * r])
                           + (1.0f - c02.x) * hi2.x;
                float ob = sigmf(acc[2 + jn][2 * r + 1]) * applyAct(ed.act, acc[jn][2 * r + 1])
                           + (1.0f - c02.y) * hi2.y;
                *(float2*)&hout[idx] = make_float2(oa, ob);
                if (ed.split) {
                    bf16 ha, la, hb, lb;
                    split1(oa, ha, la); split1(ob, hb, lb);
                    const size_t sidx = (size_t)m * KP + n;
                    *(u32*)&g_hhi[ed.child][sidx] = b2u(ha, hb);
                    *(u32*)&g_hlo[ed.child][sidx] = b2u(la, lb);
                }
            }
        }
}

// ---------------------------------------------------------------------------
// Last level fused: edges 8 (4->5, relu) and 9 (4->11, sigmoid) + leaf mean.
// NB=4: B groups [Wh8, Wc8, Wh9, Wc9].
// ---------------------------------------------------------------------------
__global__ __launch_bounds__(128) void last_mma(int t)
{
    extern __shared__ char smem[];
    const int n0 = blockIdx.x * 16;
    const bf16* base_hi[4] = { g_Whhi + (size_t)8 * 1000 * KP, g_Wchi + (size_t)8 * 1000 * KP,
                               g_Whhi + (size_t)9 * 1000 * KP, g_Wchi + (size_t)9 * 1000 * KP };
    const bf16* base_lo[4] = { g_Whlo + (size_t)8 * 1000 * KP, g_Wclo + (size_t)8 * 1000 * KP,
                               g_Whlo + (size_t)9 * 1000 * KP, g_Wclo + (size_t)9 * 1000 * KP };

    float acc[8][4] = {};
    run_pipeline<4>(smem, g_hhi[4], g_hlo[4],
        [](int m) { return m; },
        [&](int row) {
            int mat = row >> 4;
            size_t n = (size_t)min(n0 + (row & 15), Hd - 1) * KP;
            return BPtr{ base_hi[mat] + n, base_lo[mat] + n };
        }, acc);

    const int w = threadIdx.x >> 5, lane = threadIdx.x & 31;
    const int g = lane >> 2, tq = lane & 3;
#pragma unroll
    for (int jn = 0; jn < 2; jn++)
#pragma unroll
        for (int r = 0; r < 2; r++) {
            const int m = 16 * w + g + 8 * r;
            const int n = n0 + jn * 8 + 2 * tq;
            if (n < Hd) {
                const int idx = m * Hd + n;
                float2 h4v = *(const float2*)&g_h[4][idx];
                float2 c02 = *(const float2*)&g_c0[idx];
                float oma = 1.0f - c02.x, omb = 1.0f - c02.y;
                float h5a  = sigmf(acc[2 + jn][2 * r])     * fmaxf(acc[jn][2 * r], 0.0f)      + oma * h4v.x;
                float h5b  = sigmf(acc[2 + jn][2 * r + 1]) * fmaxf(acc[jn][2 * r + 1], 0.0f)  + omb * h4v.y;
                float h11a = sigmf(acc[6 + jn][2 * r])     * sigmf(acc[4 + jn][2 * r])        + oma * h4v.x;
                float h11b = sigmf(acc[6 + jn][2 * r + 1]) * sigmf(acc[4 + jn][2 * r + 1])    + omb * h4v.y;
                *(float2*)&g_h[11][idx] = make_float2(h11a, h11b);
                bf16 ha, la, hb, lb;
                split1(h11a, ha, la); split1(h11b, hb, lb);
                const size_t sidx = (size_t)m * KP + n;
                *(u32*)&g_hhi[11][sidx] = b2u(ha, hb);
                *(u32*)&g_hlo[11][sidx] = b2u(la, lb);

                float2 h7 = *(const float2*)&g_h[7][idx];
                float2 h8 = *(const float2*)&g_h[8][idx];
                float2 h9 = *(const float2*)&g_h[9][idx];
                float2 hA = *(const float2*)&g_h[10][idx];
                float oa = (h5a + h11a + h7.x + h8.x + h9.x + hA.x) * (1.0f / 6.0f);
                float ob = (h5b + h11b + h7.y + h8.y + h9.y + hA.y) * (1.0f / 6.0f);
                split1(oa, ha, la); split1(ob, hb, lb);
                const size_t oidx = (size_t)(t * Bb + m) * KP + n;
                *(u32*)&g_outshi[oidx] = b2u(ha, hb);
                *(u32*)&g_outslo[oidx] = b2u(la, lb);
            }
        }
}

// ---------------------------------------------------------------------------
// Decoder: out[m][v] = outs[m] . dec_w[v] + dec_b[v]; grid (313, 64).
// ---------------------------------------------------------------------------
__global__ __launch_bounds__(128) void decoder_mma(
    const float* __restrict__ dec_b, float* __restrict__ out)
{
    extern __shared__ char smem[];
    const int n0 = blockIdx.x * 32;
    const int m0 = blockIdx.y * 64;
    float acc[4][4] = {};
    run_pipeline<2>(smem, g_outshi, g_outslo,
        [&](int m) { return m0 + m; },
        [&](int row) {
            size_t n = (size_t)min(n0 + row, Vv - 1) * KP;
            return BPtr{ g_dechi + n, g_declo + n };
        }, acc);

    const int w = threadIdx.x >> 5, lane = threadIdx.x & 31;
    const int g = lane >> 2, tq = lane & 3;
#pragma unroll
    for (int j = 0; j < 4; j++)
#pragma unroll
        for (int r = 0; r < 2; r++) {
            const int m = m0 + 16 * w + g + 8 * r;
            const int n = n0 + (j >> 1) * 16 + (j & 1) * 8 + 2 * tq;
            if (n < Vv) {
                float2 db = *(const float2*)&dec_b[n];
                *(float2*)&out[(size_t)m * Vv + n] =
                    make_float2(acc[j][2 * r] + db.x, acc[j][2 * r + 1] + db.y);
            }
        }
}

} // namespace

// ---------------------------------------------------------------------------
extern "C" void kernel_launch(void* const* d_in, const int* in_sizes, int n_in,
                              void* d_out, int out_size)
{
    (void)in_sizes; (void)n_in; (void)out_size;

    const int*   inputs = (const int*)  d_in[0];
    const float* hidden = (const float*)d_in[1];
    const float* emb    = (const float*)d_in[2];
    const float* w_xh   = (const float*)d_in[3];
    const float* b_xh   = (const float*)d_in[4];
    const float* w_xc   = (const float*)d_in[5];
    const float* b_xc   = (const float*)d_in[6];
    const float* Wh     = (const float*)d_in[7];
    const float* Wc     = (const float*)d_in[8];
    const float* dec_w  = (const float*)d_in[9];
    const float* dec_b  = (const float*)d_in[10];
    float* out = (float*)d_out;

    cudaFuncSetAttribute(precomp_mma, cudaFuncAttributeMaxDynamicSharedMemorySize, SMEM_NB2);
    cudaFuncSetAttribute(cell0_mma,   cudaFuncAttributeMaxDynamicSharedMemorySize, SMEM_NB2);
    cudaFuncSetAttribute(level_mma,   cudaFuncAttributeMaxDynamicSharedMemorySize, SMEM_NB2);
    cudaFuncSetAttribute(last_mma,    cudaFuncAttributeMaxDynamicSharedMemorySize, SMEM_NB4);
    cudaFuncSetAttribute(decoder_mma, cudaFuncAttributeMaxDynamicSharedMemorySize, SMEM_NB2);

    // acts: 0=relu, 1=tanh, 2=sigmoid, 3=identity; split=1 if child is a parent
    const LevelDesc LV1 = {{ {0, 1, 0, 0, 1},  {0, 6, 1, 1, 1},  {0, 0, 0, 3, 0} }};
    const LevelDesc LV2 = {{ {1, 2, 2, 0, 1},  {1, 8, 3, 2, 0},  {6, 7, 10, 1, 0} }};
    const LevelDesc LV3 = {{ {2, 3, 4, 1, 1},  {2, 9, 5, 0, 0},  {0, 0, 0, 3, 0} }};
    const LevelDesc LV4 = {{ {3, 4, 6, 3, 1},  {3, 10, 7, 1, 0}, {0, 0, 0, 3, 0} }};

    prep_split<<<(PREP_UNITS + 255) / 256, 256>>>(Wh, Wc, dec_w, emb, hidden, w_xh, w_xc);
    precomp_mma<<<dim3(63, 64), 128, SMEM_NB2>>>(inputs, b_xh, b_xc);

    for (int t = 0; t < Tt; ++t) {
        cell0_mma<<<63, 128, SMEM_NB2>>>(hidden, t);
        level_mma<<<dim3(63, 2), 128, SMEM_NB2>>>(LV1);
        level_mma<<<dim3(63, 3), 128, SMEM_NB2>>>(LV2);
        level_mma<<<dim3(63, 2), 128, SMEM_NB2>>>(LV3);
        level_mma<<<dim3(63, 2), 128, SMEM_NB2>>>(LV4);
        last_mma<<<63, 128, SMEM_NB4>>>(t);
    }

    decoder_mma<<<dim3((Vv + 31) / 32, Tt * Bb / 64), 128, SMEM_NB2>>>(dec_b, out);
}